// round 4
// baseline (speedup 1.0000x reference)
#include <cuda_runtime.h>
#include <cuda_fp16.h>
#include <cstdint>
#include <math.h>

#define NTOK 8192
#define HD   1024
#define ID   4096
#define NE   8

// ---------------- scratch (static device globals; no allocs) ----------------
__device__ __align__(256) __half g_W1h[(size_t)NE * HD * ID];   // 64 MB  [E][H][I]  (K-major rows for mma B)
__device__ __align__(256) __half g_Woh[(size_t)ID * HD];        // 8 MB   [I][H]
__device__ __align__(256) __half g_xh[(size_t)NTOK * HD];       // 16 MB  permuted fp16 activations
__device__ __align__(256) __half g_inter[(size_t)NTOK * ID];    // 64 MB  permuted
__device__ __align__(256) float  g_y[(size_t)NTOK * HD];        // 32 MB  permuted, +bo
__device__ int g_expert[NTOK];
__device__ int g_perm[NTOK];
__device__ int g_counts[NE];
__device__ int g_offsets[NE + 1];
__device__ int g_cursor[NE];

// ---------------- helpers ----------------
__device__ __forceinline__ void cpa16(void* s, const void* g) {
    uint32_t a = (uint32_t)__cvta_generic_to_shared(s);
    asm volatile("cp.async.cg.shared.global [%0], [%1], 16;" :: "r"(a), "l"(g));
}
__device__ __forceinline__ void ldsm4(uint32_t& r0, uint32_t& r1, uint32_t& r2, uint32_t& r3, const void* p) {
    uint32_t a = (uint32_t)__cvta_generic_to_shared(p);
    asm volatile("ldmatrix.sync.aligned.m8n8.x4.shared.b16 {%0,%1,%2,%3}, [%4];"
                 : "=r"(r0), "=r"(r1), "=r"(r2), "=r"(r3) : "r"(a));
}
__device__ __forceinline__ void ldsm4t(uint32_t& r0, uint32_t& r1, uint32_t& r2, uint32_t& r3, const void* p) {
    uint32_t a = (uint32_t)__cvta_generic_to_shared(p);
    asm volatile("ldmatrix.sync.aligned.m8n8.x4.trans.shared.b16 {%0,%1,%2,%3}, [%4];"
                 : "=r"(r0), "=r"(r1), "=r"(r2), "=r"(r3) : "r"(a));
}
__device__ __forceinline__ void mma16816(float c[4], const uint32_t a[4], const uint32_t b[2]) {
    asm volatile("mma.sync.aligned.m16n8k16.row.col.f32.f16.f16.f32 "
                 "{%0,%1,%2,%3}, {%4,%5,%6,%7}, {%8,%9}, {%0,%1,%2,%3};"
                 : "+f"(c[0]), "+f"(c[1]), "+f"(c[2]), "+f"(c[3])
                 : "r"(a[0]), "r"(a[1]), "r"(a[2]), "r"(a[3]), "r"(b[0]), "r"(b[1]));
}
__device__ __forceinline__ float gelu_exact(float v) {
    return 0.5f * v * (1.0f + erff(v * 0.70710678118654752f));
}

// ---------------- pipeline kernels ----------------
// fp32 -> fp16 weight conversion (also zeroes MoE counters from block 0)
__global__ void convert_kernel(const float4* __restrict__ W1, const float4* __restrict__ Wo) {
    if (blockIdx.x == 0 && threadIdx.x < NE) {
        g_counts[threadIdx.x] = 0; g_cursor[threadIdx.x] = 0;
    }
    size_t i = (size_t)blockIdx.x * blockDim.x + threadIdx.x;
    const size_t n1 = (size_t)NE * HD * ID / 4;
    const size_t n2 = (size_t)ID * HD / 4;
    if (i < n1) {
        float4 v = W1[i];
        __half2* d = (__half2*)g_W1h;
        d[2 * i]     = __floats2half2_rn(v.x, v.y);
        d[2 * i + 1] = __floats2half2_rn(v.z, v.w);
    } else if (i < n1 + n2) {
        size_t j = i - n1;
        float4 v = Wo[j];
        __half2* d = (__half2*)g_Woh;
        d[2 * j]     = __floats2half2_rn(v.x, v.y);
        d[2 * j + 1] = __floats2half2_rn(v.z, v.w);
    }
}

// router: fp32 logits + argmax (first-max tie-break == jnp.argmax)
__global__ void router_kernel(const float* __restrict__ x, const float* __restrict__ Wr) {
    __shared__ float4 Wrs[NE * 256];
    int tid = threadIdx.x;
    const float4* Wr4 = (const float4*)Wr;
    for (int i = tid; i < NE * 256; i += 256) Wrs[i] = Wr4[i];
    __syncthreads();
    int warp = tid >> 5, lane = tid & 31;
    int n = blockIdx.x * 8 + warp;
    const float4* xr = (const float4*)(x + (size_t)n * HD);
    float acc[NE];
#pragma unroll
    for (int e = 0; e < NE; e++) acc[e] = 0.f;
#pragma unroll
    for (int j = 0; j < 8; j++) {
        float4 v = xr[j * 32 + lane];
#pragma unroll
        for (int e = 0; e < NE; e++) {
            float4 w = Wrs[e * 256 + j * 32 + lane];
            acc[e] += v.x * w.x + v.y * w.y + v.z * w.z + v.w * w.w;
        }
    }
#pragma unroll
    for (int e = 0; e < NE; e++)
#pragma unroll
        for (int o = 16; o > 0; o >>= 1) acc[e] += __shfl_xor_sync(0xffffffffu, acc[e], o);
    if (lane == 0) {
        int best = 0; float bv = acc[0];
#pragma unroll
        for (int e = 1; e < NE; e++) if (acc[e] > bv) { bv = acc[e]; best = e; }
        g_expert[n] = best;
        atomicAdd(&g_counts[best], 1);
    }
}

__global__ void scan_kernel() {
    int off = 0;
    for (int e = 0; e < NE; e++) { g_offsets[e] = off; off += g_counts[e]; }
    g_offsets[NE] = off;
}

__global__ void scatter_kernel() {
    int t = blockIdx.x * 256 + threadIdx.x;
    if (t >= NTOK) return;
    int e = g_expert[t];
    int pos = g_offsets[e] + atomicAdd(&g_cursor[e], 1);
    g_perm[pos] = t;
}

__global__ void gather_kernel(const float* __restrict__ x) {
    int pos = blockIdx.x;
    int tok = g_perm[pos];
    const float4* src = (const float4*)(x + (size_t)tok * HD);
    __half2* dst = (__half2*)(g_xh + (size_t)pos * HD);
    for (int i = threadIdx.x; i < 256; i += 128) {
        float4 v = src[i];
        dst[2 * i]     = __floats2half2_rn(v.x, v.y);
        dst[2 * i + 1] = __floats2half2_rn(v.z, v.w);
    }
}

// ---------------- fp16 HMMA GEMM core ----------------
// CTA tile 128x256, K-stage 64, 3-stage cp.async pipeline, 8 warps (2x4),
// warp tile 64x64 -> 8 ldmatrix per 32 mma. XOR-swizzled smem (16B granules).
// A [M,K] row-major fp16, B [K,N] row-major fp16.
#define NST 3
#define A_BYT (128 * 128)            // 128 rows * 64 halves
#define B_BYT (64 * 512)             // 64 rows * 256 halves
#define ST_BYT (A_BYT + B_BYT)       // 49152
#define GEMM_SMEM (NST * ST_BYT)     // 147456

template <int EPI>
__device__ __forceinline__ void gemm_core(
    const __half* __restrict__ A, int lda,
    const __half* __restrict__ B, int ldb,
    const float* __restrict__ bias,
    int M, int K,
    __half* __restrict__ outH, float* __restrict__ outF, int ldc,
    int m0, int n0, char* smem)
{
    const int tid = threadIdx.x;
    const int lane = tid & 31, wid = tid >> 5;
    const int wm = wid >> 2, wn = wid & 3;      // 2 x 4 warp grid

    float acc[4][8][4];
#pragma unroll
    for (int i = 0; i < 4; i++)
#pragma unroll
        for (int j = 0; j < 8; j++)
#pragma unroll
            for (int k = 0; k < 4; k++) acc[i][j][k] = 0.f;

    const int nk = K >> 6;

    auto load_stage = [&](int s) {
        char* base = smem + (s % NST) * ST_BYT;
        char* as = base;
        char* bs = base + A_BYT;
        const int k0 = s << 6;
#pragma unroll
        for (int i = 0; i < 4; i++) {            // A: 128 rows x 8 granules
            int c = tid + (i << 8);
            int r = c >> 3, g = c & 7;
            int gr = m0 + r; if (gr >= M) gr = M - 1;   // clamp (tail rows never stored)
            cpa16(as + (r << 7) + ((g ^ (r & 7)) << 4),
                  A + (size_t)gr * lda + k0 + (g << 3));
        }
#pragma unroll
        for (int i = 0; i < 8; i++) {            // B: 64 rows x 32 granules
            int c = tid + (i << 8);
            int r = c >> 5, g = c & 31;
            cpa16(bs + (r << 9) + (((g & 24) | ((g ^ (r & 7)) & 7)) << 4),
                  B + (size_t)(k0 + r) * ldb + n0 + (g << 3));
        }
        asm volatile("cp.async.commit_group;" ::: "memory");
    };

    load_stage(0);
    load_stage(1);

    for (int kt = 0; kt < nk; kt++) {
        if (kt > 0) __syncthreads();             // all warps done with stage kt-1's buffer
        if (kt + 2 < nk) {
            load_stage(kt + 2);
            asm volatile("cp.async.wait_group 2;" ::: "memory");
        } else if (kt + 1 < nk) {
            asm volatile("cp.async.wait_group 1;" ::: "memory");
        } else {
            asm volatile("cp.async.wait_group 0;" ::: "memory");
        }
        __syncthreads();

        char* base = smem + (kt % NST) * ST_BYT;
        char* as = base;
        char* bs = base + A_BYT;
#pragma unroll
        for (int ks = 0; ks < 4; ks++) {
            uint32_t af[4][4];
#pragma unroll
            for (int mi = 0; mi < 4; mi++) {
                int mr = wm * 64 + mi * 16 + (lane & 15);
                int ga = ks * 2 + (lane >> 4);
                ldsm4(af[mi][0], af[mi][1], af[mi][2], af[mi][3],
                      as + (mr << 7) + ((ga ^ (mr & 7)) << 4));
            }
            uint32_t bf[8][2];
#pragma unroll
            for (int nj = 0; nj < 4; nj++) {
                int kr = ks * 16 + (lane & 15);
                int g = wn * 8 + nj * 2 + (lane >> 4);
                ldsm4t(bf[2 * nj][0], bf[2 * nj][1], bf[2 * nj + 1][0], bf[2 * nj + 1][1],
                       bs + (kr << 9) + (((g & 24) | ((g ^ (kr & 7)) & 7)) << 4));
            }
#pragma unroll
            for (int mi = 0; mi < 4; mi++)
#pragma unroll
                for (int ni = 0; ni < 8; ni++)
                    mma16816(acc[mi][ni], af[mi], bf[ni]);
        }
    }

    // epilogue: c0:(g,2t) c1:(g,2t+1) c2:(g+8,2t) c3:(g+8,2t+1)
    const int gq = lane >> 2, tq = lane & 3;
#pragma unroll
    for (int mi = 0; mi < 4; mi++) {
#pragma unroll
        for (int rr = 0; rr < 2; rr++) {
            int lr = wm * 64 + mi * 16 + gq + rr * 8;
            int grow = m0 + lr;
            if (grow < M) {
#pragma unroll
                for (int ni = 0; ni < 8; ni++) {
                    int col = n0 + wn * 64 + ni * 8 + tq * 2;
                    float v0 = acc[mi][ni][rr * 2 + 0] + bias[col];
                    float v1 = acc[mi][ni][rr * 2 + 1] + bias[col + 1];
                    if (EPI == 1) {
                        v0 = gelu_exact(v0);
                        v1 = gelu_exact(v1);
                        *(__half2*)(outH + (size_t)grow * ldc + col) = __floats2half2_rn(v0, v1);
                    } else {
                        float2 f; f.x = v0; f.y = v1;
                        *(float2*)(outF + (size_t)grow * ldc + col) = f;
                    }
                }
            }
        }
    }
}

// grouped GEMM1: inter = gelu(xh @ W1[e] + b1[e]); per-expert contiguous rows
__global__ __launch_bounds__(256, 1) void gemm1_kernel(const float* __restrict__ b1) {
    extern __shared__ char smem[];
    int e = blockIdx.z;
    int off = g_offsets[e];
    int Me = g_offsets[e + 1] - off;
    int m0 = blockIdx.y << 7;
    if (m0 >= Me) return;
    gemm_core<1>(g_xh + (size_t)off * HD, HD,
                 g_W1h + (size_t)e * HD * ID, ID,
                 b1 + (size_t)e * ID, Me, HD,
                 g_inter + (size_t)off * ID, nullptr, ID,
                 m0, blockIdx.x << 8, smem);
}

// dense GEMM2: y = inter @ Wo + bo
__global__ __launch_bounds__(256, 1) void gemm2_kernel(const float* __restrict__ bo) {
    extern __shared__ char smem[];
    gemm_core<2>(g_inter, ID, g_Woh, HD, bo, NTOK, ID,
                 nullptr, g_y, HD, blockIdx.y << 7, blockIdx.x << 8, smem);
}

// ---------------- LayerNorm epilogue with exact fp32 residual + un-permute ----------------
__global__ void ln_kernel(const float* __restrict__ x, const float* __restrict__ gamma,
                          const float* __restrict__ beta, float* __restrict__ out) {
    int pos = blockIdx.x;
    int tok = g_perm[pos];
    const float* yr = g_y + (size_t)pos * HD;
    const float* xr = x + (size_t)tok * HD;
    int tid = threadIdx.x;
    float v[4]; float s = 0.f, s2 = 0.f;
#pragma unroll
    for (int j = 0; j < 4; j++) {
        int i = tid + j * 256;
        v[j] = yr[i] + xr[i];
        s += v[j]; s2 += v[j] * v[j];
    }
    __shared__ float red[64];
#pragma unroll
    for (int o = 16; o > 0; o >>= 1) {
        s  += __shfl_xor_sync(0xffffffffu, s, o);
        s2 += __shfl_xor_sync(0xffffffffu, s2, o);
    }
    int w = tid >> 5;
    if ((tid & 31) == 0) { red[w] = s; red[32 + w] = s2; }
    __syncthreads();
    if (tid < 32) {
        float a = (tid < 8) ? red[tid] : 0.f;
        float b = (tid < 8) ? red[32 + tid] : 0.f;
#pragma unroll
        for (int o = 4; o > 0; o >>= 1) {
            a += __shfl_xor_sync(0xffffffffu, a, o);
            b += __shfl_xor_sync(0xffffffffu, b, o);
        }
        if (tid == 0) { red[0] = a; red[32] = b; }
    }
    __syncthreads();
    float mu = red[0] * (1.0f / HD);
    float var = red[32] * (1.0f / HD) - mu * mu;
    float rs = rsqrtf(var + 1e-12f);
    float* orow = out + (size_t)tok * HD;
#pragma unroll
    for (int j = 0; j < 4; j++) {
        int i = tid + j * 256;
        orow[i] = (v[j] - mu) * rs * gamma[i] + beta[i];
    }
}

// ---------------- launch ----------------
extern "C" void kernel_launch(void* const* d_in, const int* in_sizes, int n_in,
                              void* d_out, int out_size) {
    const float* x     = (const float*)d_in[0];
    const float* Wr    = (const float*)d_in[1];
    const float* W1    = (const float*)d_in[2];
    const float* b1    = (const float*)d_in[3];
    const float* Wo    = (const float*)d_in[4];
    const float* bo    = (const float*)d_in[5];
    const float* gamma = (const float*)d_in[6];
    const float* beta  = (const float*)d_in[7];
    float* out = (float*)d_out;
    (void)in_sizes; (void)n_in; (void)out_size;

    cudaFuncSetAttribute(gemm1_kernel, cudaFuncAttributeMaxDynamicSharedMemorySize, GEMM_SMEM);
    cudaFuncSetAttribute(gemm2_kernel, cudaFuncAttributeMaxDynamicSharedMemorySize, GEMM_SMEM);

    convert_kernel<<<36864, 256>>>((const float4*)W1, (const float4*)Wo);  // launch 1
    router_kernel<<<1024, 256>>>(x, Wr);                                   // launch 2
    scan_kernel<<<1, 1>>>();                                               // launch 3
    scatter_kernel<<<32, 256>>>();                                         // launch 4
    gather_kernel<<<8192, 128>>>(x);                                       // launch 5

    dim3 g1(ID / 256, NTOK / 128, NE);   // 16 x 64 x 8; empty m-tiles exit early
    gemm1_kernel<<<g1, 256, GEMM_SMEM>>>(b1);                              // launch 6 (ncu -s 5 -c 1)

    dim3 g2(HD / 256, NTOK / 128, 1);    // 4 x 64
    gemm2_kernel<<<g2, 256, GEMM_SMEM>>>(bo);

    ln_kernel<<<8192, 256>>>(x, gamma, beta, out);
}

// round 5
// speedup vs baseline: 1.6611x; 1.6611x over previous
#include <cuda_runtime.h>
#include <cuda_fp16.h>
#include <cstdint>
#include <math.h>

#define NTOK 8192
#define HD   1024
#define ID   4096
#define NE   8

// ---------------- scratch (static device globals; no allocs) ----------------
__device__ __align__(256) __half g_W1h[(size_t)NE * HD * ID];   // 64 MB  [E][H][I]
__device__ __align__(256) __half g_Woh[(size_t)ID * HD];        // 8 MB   [I][H]
__device__ __align__(256) __half g_xh[(size_t)NTOK * HD];       // 16 MB  UNPERMUTED fp16 activations
__device__ __align__(256) __half g_inter[(size_t)NTOK * ID];    // 64 MB  permuted
__device__ __align__(256) float  g_y[(size_t)NTOK * HD];        // 32 MB  permuted, +bo
__device__ int g_expert[NTOK];
__device__ int g_perm[NTOK];
__device__ int g_counts[NE];
__device__ int g_offsets[NE + 1];
__device__ int g_cursor[NE];

// ---------------- helpers ----------------
__device__ __forceinline__ void cpa16(void* s, const void* g) {
    uint32_t a = (uint32_t)__cvta_generic_to_shared(s);
    asm volatile("cp.async.cg.shared.global [%0], [%1], 16;" :: "r"(a), "l"(g));
}
__device__ __forceinline__ void ldsm4(uint32_t& r0, uint32_t& r1, uint32_t& r2, uint32_t& r3, const void* p) {
    uint32_t a = (uint32_t)__cvta_generic_to_shared(p);
    asm volatile("ldmatrix.sync.aligned.m8n8.x4.shared.b16 {%0,%1,%2,%3}, [%4];"
                 : "=r"(r0), "=r"(r1), "=r"(r2), "=r"(r3) : "r"(a));
}
__device__ __forceinline__ void ldsm4t(uint32_t& r0, uint32_t& r1, uint32_t& r2, uint32_t& r3, const void* p) {
    uint32_t a = (uint32_t)__cvta_generic_to_shared(p);
    asm volatile("ldmatrix.sync.aligned.m8n8.x4.trans.shared.b16 {%0,%1,%2,%3}, [%4];"
                 : "=r"(r0), "=r"(r1), "=r"(r2), "=r"(r3) : "r"(a));
}
__device__ __forceinline__ void mma16816(float c[4], const uint32_t a[4], const uint32_t b[2]) {
    asm volatile("mma.sync.aligned.m16n8k16.row.col.f32.f16.f16.f32 "
                 "{%0,%1,%2,%3}, {%4,%5,%6,%7}, {%8,%9}, {%0,%1,%2,%3};"
                 : "+f"(c[0]), "+f"(c[1]), "+f"(c[2]), "+f"(c[3])
                 : "r"(a[0]), "r"(a[1]), "r"(a[2]), "r"(a[3]), "r"(b[0]), "r"(b[1]));
}
__device__ __forceinline__ float gelu_exact(float v) {
    return 0.5f * v * (1.0f + erff(v * 0.70710678118654752f));
}

// ---------------- launch 1: convert weights + activations to fp16; zero counters ----------------
__global__ void convert_kernel(const float4* __restrict__ W1, const float4* __restrict__ Wo,
                               const float4* __restrict__ x) {
    if (blockIdx.x == 0 && threadIdx.x < NE) {
        g_counts[threadIdx.x] = 0; g_cursor[threadIdx.x] = 0;
    }
    size_t i = (size_t)blockIdx.x * blockDim.x + threadIdx.x;
    const size_t n1 = (size_t)NE * HD * ID / 4;      // 8388608
    const size_t n2 = (size_t)ID * HD / 4;           // 1048576
    const size_t n3 = (size_t)NTOK * HD / 4;         // 2097152
    if (i < n1) {
        float4 v = W1[i];
        __half2* d = (__half2*)g_W1h;
        d[2 * i]     = __floats2half2_rn(v.x, v.y);
        d[2 * i + 1] = __floats2half2_rn(v.z, v.w);
    } else if (i < n1 + n2) {
        size_t j = i - n1;
        float4 v = Wo[j];
        __half2* d = (__half2*)g_Woh;
        d[2 * j]     = __floats2half2_rn(v.x, v.y);
        d[2 * j + 1] = __floats2half2_rn(v.z, v.w);
    } else if (i < n1 + n2 + n3) {
        size_t j = i - n1 - n2;
        float4 v = x[j];
        __half2* d = (__half2*)g_xh;
        d[2 * j]     = __floats2half2_rn(v.x, v.y);
        d[2 * j + 1] = __floats2half2_rn(v.z, v.w);
    }
}

// ---------------- launch 2: router (fp32 logits + first-max argmax == jnp.argmax) ----------------
__global__ void router_kernel(const float* __restrict__ x, const float* __restrict__ Wr) {
    __shared__ float4 Wrs[NE * 256];
    int tid = threadIdx.x;
    const float4* Wr4 = (const float4*)Wr;
    for (int i = tid; i < NE * 256; i += 256) Wrs[i] = Wr4[i];
    __syncthreads();
    int warp = tid >> 5, lane = tid & 31;
    int n = blockIdx.x * 8 + warp;
    const float4* xr = (const float4*)(x + (size_t)n * HD);
    float acc[NE];
#pragma unroll
    for (int e = 0; e < NE; e++) acc[e] = 0.f;
#pragma unroll
    for (int j = 0; j < 8; j++) {
        float4 v = xr[j * 32 + lane];
#pragma unroll
        for (int e = 0; e < NE; e++) {
            float4 w = Wrs[e * 256 + j * 32 + lane];
            acc[e] += v.x * w.x + v.y * w.y + v.z * w.z + v.w * w.w;
        }
    }
#pragma unroll
    for (int e = 0; e < NE; e++)
#pragma unroll
        for (int o = 16; o > 0; o >>= 1) acc[e] += __shfl_xor_sync(0xffffffffu, acc[e], o);
    if (lane == 0) {
        int best = 0; float bv = acc[0];
#pragma unroll
        for (int e = 1; e < NE; e++) if (acc[e] > bv) { bv = acc[e]; best = e; }
        g_expert[n] = best;
        atomicAdd(&g_counts[best], 1);
    }
}

// ---------------- launch 3: fused scan + scatter ----------------
__global__ void scatter_kernel() {
    int off[NE]; int a = 0;
#pragma unroll
    for (int e = 0; e < NE; e++) { off[e] = a; a += g_counts[e]; }
    if (blockIdx.x == 0 && threadIdx.x == 0) {
#pragma unroll
        for (int e = 0; e < NE; e++) g_offsets[e] = off[e];
        g_offsets[NE] = a;
    }
    int t = blockIdx.x * 256 + threadIdx.x;
    if (t < NTOK) {
        int e = g_expert[t];
        int pos = off[e] + atomicAdd(&g_cursor[e], 1);
        g_perm[pos] = t;
    }
}

// ---------------- fp16 HMMA GEMM core (round-2 layout, 3-stage, 1 sync/iter) ----------------
// CTA tile 128x128, K-stage 64, 8 warps (4x2), warp tile 32x64, 2 CTAs/SM.
// A [*,K] row-major fp16 (optionally row-indirected via s_perm), B [K,N] row-major fp16.
#define NST 3
#define A_BYT (128 * 128)            // 128 rows * 64 halves * 2B = 16KB
#define B_BYT (64 * 256)             // 64 rows * 128 halves * 2B = 16KB
#define ST_BYT (A_BYT + B_BYT)       // 32768
#define GEMM_SMEM (NST * ST_BYT + 512)   // 98816 (512B for s_perm)

template <int EPI, bool PERM>
__device__ __forceinline__ void gemm_core(
    const __half* __restrict__ A, int lda,
    const __half* __restrict__ B, int ldb,
    const float* __restrict__ bias,
    int M, int K,
    __half* __restrict__ outH, float* __restrict__ outF, int ldc,
    int m0, int n0, char* smem, const int* __restrict__ perm)
{
    const int tid = threadIdx.x;
    const int lane = tid & 31, wid = tid >> 5;
    const int wm = wid >> 1, wn = wid & 1;      // 4 x 2 warp grid

    int* s_perm = (int*)(smem + NST * ST_BYT);
    if (PERM) {
        if (tid < 128) {
            int r = m0 + tid;
            if (r >= M) r = M - 1;
            s_perm[tid] = perm[r];
        }
        __syncthreads();
    }

    float acc[2][8][4];
#pragma unroll
    for (int i = 0; i < 2; i++)
#pragma unroll
        for (int j = 0; j < 8; j++)
#pragma unroll
            for (int k = 0; k < 4; k++) acc[i][j][k] = 0.f;

    const int nk = K >> 6;

    auto load_stage = [&](int s) {
        char* base = smem + (s % NST) * ST_BYT;
        __half* as = (__half*)base;
        __half* bs = (__half*)(base + A_BYT);
        const int k0 = s << 6;
#pragma unroll
        for (int i = 0; i < 4; i++) {            // A: 128 rows x 8 granules of 16B
            int c = tid + (i << 8);
            int r = c >> 3, g = c & 7;
            const __half* src;
            if (PERM) {
                src = A + (size_t)s_perm[r] * lda + k0 + (g << 3);
            } else {
                int gr = m0 + r; if (gr >= M) gr = M - 1;
                src = A + (size_t)gr * lda + k0 + (g << 3);
            }
            cpa16(as + r * 64 + ((g ^ (r & 7)) << 3), src);
        }
#pragma unroll
        for (int i = 0; i < 4; i++) {            // B: 64 rows x 16 granules of 16B
            int c = tid + (i << 8);
            int r = c >> 4, g = c & 15;
            cpa16(bs + r * 128 + ((g ^ (r & 7)) << 3),
                  B + (size_t)(k0 + r) * ldb + n0 + (g << 3));
        }
        asm volatile("cp.async.commit_group;" ::: "memory");
    };

    load_stage(0);
    load_stage(1);

    for (int kt = 0; kt < nk; kt++) {
        if (kt + 1 < nk) {
            asm volatile("cp.async.wait_group 1;" ::: "memory");
        } else {
            asm volatile("cp.async.wait_group 0;" ::: "memory");
        }
        __syncthreads();                         // stage kt ready AND buffer (kt+2)%3 free
        if (kt + 2 < nk) load_stage(kt + 2);

        char* base = smem + (kt % NST) * ST_BYT;
        __half* as = (__half*)base;
        __half* bs = (__half*)(base + A_BYT);
#pragma unroll
        for (int ks = 0; ks < 4; ks++) {
            const int kk = ks << 4;
            uint32_t af[2][4];
#pragma unroll
            for (int mi = 0; mi < 2; mi++) {
                int mr = wm * 32 + mi * 16 + (lane & 15);
                int g = (kk >> 3) + (lane >> 4);
                ldsm4(af[mi][0], af[mi][1], af[mi][2], af[mi][3],
                      as + mr * 64 + ((g ^ (mr & 7)) << 3));
            }
            uint32_t bf[8][2];
#pragma unroll
            for (int nj = 0; nj < 4; nj++) {
                int kr = kk + (lane & 15);
                int g = wn * 8 + nj * 2 + (lane >> 4);
                ldsm4t(bf[2 * nj][0], bf[2 * nj][1], bf[2 * nj + 1][0], bf[2 * nj + 1][1],
                       bs + kr * 128 + ((g ^ (kr & 7)) << 3));
            }
#pragma unroll
            for (int mi = 0; mi < 2; mi++)
#pragma unroll
                for (int ni = 0; ni < 8; ni++)
                    mma16816(acc[mi][ni], af[mi], bf[ni]);
        }
    }

    // epilogue: c0:(g,2t) c1:(g,2t+1) c2:(g+8,2t) c3:(g+8,2t+1)
    const int gq = lane >> 2, tq = lane & 3;
#pragma unroll
    for (int mi = 0; mi < 2; mi++) {
#pragma unroll
        for (int rr = 0; rr < 2; rr++) {
            int lr = wm * 32 + mi * 16 + gq + rr * 8;
            int grow = m0 + lr;
            if (grow < M) {
#pragma unroll
                for (int ni = 0; ni < 8; ni++) {
                    int col = n0 + wn * 64 + ni * 8 + tq * 2;
                    float v0 = acc[mi][ni][rr * 2 + 0] + bias[col];
                    float v1 = acc[mi][ni][rr * 2 + 1] + bias[col + 1];
                    if (EPI == 1) {
                        v0 = gelu_exact(v0);
                        v1 = gelu_exact(v1);
                        *(__half2*)(outH + (size_t)grow * ldc + col) = __floats2half2_rn(v0, v1);
                    } else {
                        float2 f; f.x = v0; f.y = v1;
                        *(float2*)(outF + (size_t)grow * ldc + col) = f;
                    }
                }
            }
        }
    }
}

// ---------------- launch 4: grouped GEMM1 (A row-gather fused via s_perm) ----------------
__global__ __launch_bounds__(256, 2) void gemm1_kernel(const float* __restrict__ b1) {
    extern __shared__ char smem[];
    int e = blockIdx.z;
    int off = g_offsets[e];
    int Me = g_offsets[e + 1] - off;
    int m0 = blockIdx.y << 7;
    if (m0 >= Me) return;
    gemm_core<1, true>(g_xh, HD,
                       g_W1h + (size_t)e * HD * ID, ID,
                       b1 + (size_t)e * ID, Me, HD,
                       g_inter + (size_t)off * ID, nullptr, ID,
                       m0, blockIdx.x << 7, smem, g_perm + off);
}

// ---------------- launch 5: dense GEMM2 ----------------
__global__ __launch_bounds__(256, 2) void gemm2_kernel(const float* __restrict__ bo) {
    extern __shared__ char smem[];
    gemm_core<2, false>(g_inter, ID, g_Woh, HD, bo, NTOK, ID,
                        nullptr, g_y, HD, blockIdx.y << 7, blockIdx.x << 7, smem, nullptr);
}

// ---------------- launch 6: LayerNorm with exact fp32 residual + un-permute ----------------
__global__ void ln_kernel(const float* __restrict__ x, const float* __restrict__ gamma,
                          const float* __restrict__ beta, float* __restrict__ out) {
    int pos = blockIdx.x;
    int tok = g_perm[pos];
    const float* yr = g_y + (size_t)pos * HD;
    const float* xr = x + (size_t)tok * HD;
    int tid = threadIdx.x;
    float v[4]; float s = 0.f, s2 = 0.f;
#pragma unroll
    for (int j = 0; j < 4; j++) {
        int i = tid + j * 256;
        v[j] = yr[i] + xr[i];
        s += v[j]; s2 += v[j] * v[j];
    }
    __shared__ float red[64];
#pragma unroll
    for (int o = 16; o > 0; o >>= 1) {
        s  += __shfl_xor_sync(0xffffffffu, s, o);
        s2 += __shfl_xor_sync(0xffffffffu, s2, o);
    }
    int w = tid >> 5;
    if ((tid & 31) == 0) { red[w] = s; red[32 + w] = s2; }
    __syncthreads();
    if (tid < 32) {
        float a = (tid < 8) ? red[tid] : 0.f;
        float b = (tid < 8) ? red[32 + tid] : 0.f;
#pragma unroll
        for (int o = 4; o > 0; o >>= 1) {
            a += __shfl_xor_sync(0xffffffffu, a, o);
            b += __shfl_xor_sync(0xffffffffu, b, o);
        }
        if (tid == 0) { red[0] = a; red[32] = b; }
    }
    __syncthreads();
    float mu = red[0] * (1.0f / HD);
    float var = red[32] * (1.0f / HD) - mu * mu;
    float rs = rsqrtf(var + 1e-12f);
    float* orow = out + (size_t)tok * HD;
#pragma unroll
    for (int j = 0; j < 4; j++) {
        int i = tid + j * 256;
        orow[i] = (v[j] - mu) * rs * gamma[i] + beta[i];
    }
}

// ---------------- launch ----------------
extern "C" void kernel_launch(void* const* d_in, const int* in_sizes, int n_in,
                              void* d_out, int out_size) {
    const float* x     = (const float*)d_in[0];
    const float* Wr    = (const float*)d_in[1];
    const float* W1    = (const float*)d_in[2];
    const float* b1    = (const float*)d_in[3];
    const float* Wo    = (const float*)d_in[4];
    const float* bo    = (const float*)d_in[5];
    const float* gamma = (const float*)d_in[6];
    const float* beta  = (const float*)d_in[7];
    float* out = (float*)d_out;
    (void)in_sizes; (void)n_in; (void)out_size;

    cudaFuncSetAttribute(gemm1_kernel, cudaFuncAttributeMaxDynamicSharedMemorySize, GEMM_SMEM);
    cudaFuncSetAttribute(gemm2_kernel, cudaFuncAttributeMaxDynamicSharedMemorySize, GEMM_SMEM);

    convert_kernel<<<45056, 256>>>((const float4*)W1, (const float4*)Wo, (const float4*)x);  // 1
    router_kernel<<<1024, 256>>>(x, Wr);                                                     // 2
    scatter_kernel<<<32, 256>>>();                                                           // 3

    dim3 g1(ID / 128, NTOK / 128, NE);   // 32 x 64 x 8; empty m-tiles exit early
    gemm1_kernel<<<g1, 256, GEMM_SMEM>>>(b1);                                                // 4 (ncu target)

    dim3 g2(HD / 128, NTOK / 128, 1);    // 8 x 64
    gemm2_kernel<<<g2, 256, GEMM_SMEM>>>(bo);                                                // 5

    ln_kernel<<<8192, 256>>>(x, gamma, beta, out);                                           // 6
}

// round 6
// speedup vs baseline: 1.6651x; 1.0024x over previous
#include <cuda_runtime.h>
#include <cuda_fp16.h>
#include <cstdint>
#include <math.h>

#define NTOK 8192
#define HD   1024
#define ID   4096
#define NE   8
#define NPAD 9216        // NTOK + NE*128 slack for per-expert padding

// ---------------- scratch (static device globals; no allocs) ----------------
__device__ __align__(256) __half g_W1h[(size_t)NE * HD * ID];   // 64 MB  [E][H][I]
__device__ __align__(256) __half g_Woh[(size_t)ID * HD];        // 8 MB   [I][H]
__device__ __align__(256) __half g_xh[(size_t)NTOK * HD];       // 16 MB  UNPERMUTED fp16 activations
__device__ __align__(256) __half g_inter[(size_t)NPAD * ID];    // 75.5 MB padded-permuted
__device__ __align__(256) __half g_yh[(size_t)NPAD * HD];       // 18.9 MB padded-permuted, +bo, fp16
__device__ int g_expert[NTOK];
__device__ int g_perm[NPAD];     // padded slots = -1
__device__ int g_counts[NE];
__device__ int g_offsets[NE + 1];  // PADDED offsets (each multiple of 128)
__device__ int g_cursor[NE];

// ---------------- helpers ----------------
__device__ __forceinline__ void cpa16(void* s, const void* g) {
    uint32_t a = (uint32_t)__cvta_generic_to_shared(s);
    asm volatile("cp.async.cg.shared.global [%0], [%1], 16;" :: "r"(a), "l"(g));
}
__device__ __forceinline__ void ldsm4(uint32_t& r0, uint32_t& r1, uint32_t& r2, uint32_t& r3, const void* p) {
    uint32_t a = (uint32_t)__cvta_generic_to_shared(p);
    asm volatile("ldmatrix.sync.aligned.m8n8.x4.shared.b16 {%0,%1,%2,%3}, [%4];"
                 : "=r"(r0), "=r"(r1), "=r"(r2), "=r"(r3) : "r"(a));
}
__device__ __forceinline__ void ldsm4t(uint32_t& r0, uint32_t& r1, uint32_t& r2, uint32_t& r3, const void* p) {
    uint32_t a = (uint32_t)__cvta_generic_to_shared(p);
    asm volatile("ldmatrix.sync.aligned.m8n8.x4.trans.shared.b16 {%0,%1,%2,%3}, [%4];"
                 : "=r"(r0), "=r"(r1), "=r"(r2), "=r"(r3) : "r"(a));
}
__device__ __forceinline__ void mma16816(float c[4], const uint32_t a[4], const uint32_t b[2]) {
    asm volatile("mma.sync.aligned.m16n8k16.row.col.f32.f16.f16.f32 "
                 "{%0,%1,%2,%3}, {%4,%5,%6,%7}, {%8,%9}, {%0,%1,%2,%3};"
                 : "+f"(c[0]), "+f"(c[1]), "+f"(c[2]), "+f"(c[3])
                 : "r"(a[0]), "r"(a[1]), "r"(a[2]), "r"(a[3]), "r"(b[0]), "r"(b[1]));
}
__device__ __forceinline__ float gelu_exact(float v) {
    return 0.5f * v * (1.0f + erff(v * 0.70710678118654752f));
}

// ---------------- launch 1: fp16 conversion + init perm/counters ----------------
__global__ void convert_kernel(const float4* __restrict__ W1, const float4* __restrict__ Wo,
                               const float4* __restrict__ x) {
    if (blockIdx.x < NPAD / 256) g_perm[blockIdx.x * 256 + threadIdx.x] = -1;
    if (blockIdx.x == 0 && threadIdx.x < NE) {
        g_counts[threadIdx.x] = 0; g_cursor[threadIdx.x] = 0;
    }
    size_t i = (size_t)blockIdx.x * blockDim.x + threadIdx.x;
    const size_t n1 = (size_t)NE * HD * ID / 4;      // 8388608
    const size_t n2 = (size_t)ID * HD / 4;           // 1048576
    const size_t n3 = (size_t)NTOK * HD / 4;         // 2097152
    if (i < n1) {
        float4 v = W1[i];
        __half2* d = (__half2*)g_W1h;
        d[2 * i]     = __floats2half2_rn(v.x, v.y);
        d[2 * i + 1] = __floats2half2_rn(v.z, v.w);
    } else if (i < n1 + n2) {
        size_t j = i - n1;
        float4 v = Wo[j];
        __half2* d = (__half2*)g_Woh;
        d[2 * j]     = __floats2half2_rn(v.x, v.y);
        d[2 * j + 1] = __floats2half2_rn(v.z, v.w);
    } else if (i < n1 + n2 + n3) {
        size_t j = i - n1 - n2;
        float4 v = x[j];
        __half2* d = (__half2*)g_xh;
        d[2 * j]     = __floats2half2_rn(v.x, v.y);
        d[2 * j + 1] = __floats2half2_rn(v.z, v.w);
    }
}

// ---------------- launch 2: router (fp32 logits + first-max argmax == jnp.argmax) ----------------
__global__ void router_kernel(const float* __restrict__ x, const float* __restrict__ Wr) {
    __shared__ float4 Wrs[NE * 256];
    int tid = threadIdx.x;
    const float4* Wr4 = (const float4*)Wr;
    for (int i = tid; i < NE * 256; i += 256) Wrs[i] = Wr4[i];
    __syncthreads();
    int warp = tid >> 5, lane = tid & 31;
    int n = blockIdx.x * 8 + warp;
    const float4* xr = (const float4*)(x + (size_t)n * HD);
    float acc[NE];
#pragma unroll
    for (int e = 0; e < NE; e++) acc[e] = 0.f;
#pragma unroll
    for (int j = 0; j < 8; j++) {
        float4 v = xr[j * 32 + lane];
#pragma unroll
        for (int e = 0; e < NE; e++) {
            float4 w = Wrs[e * 256 + j * 32 + lane];
            acc[e] += v.x * w.x + v.y * w.y + v.z * w.z + v.w * w.w;
        }
    }
#pragma unroll
    for (int e = 0; e < NE; e++)
#pragma unroll
        for (int o = 16; o > 0; o >>= 1) acc[e] += __shfl_xor_sync(0xffffffffu, acc[e], o);
    if (lane == 0) {
        int best = 0; float bv = acc[0];
#pragma unroll
        for (int e = 1; e < NE; e++) if (acc[e] > bv) { bv = acc[e]; best = e; }
        g_expert[n] = best;
        atomicAdd(&g_counts[best], 1);
    }
}

// ---------------- launch 3: fused scan (padded) + scatter ----------------
__global__ void scatter_kernel() {
    int off[NE]; int a = 0;
#pragma unroll
    for (int e = 0; e < NE; e++) {
        off[e] = a;
        a += (g_counts[e] + 127) & ~127;    // pad each expert block to 128 rows
    }
    if (blockIdx.x == 0 && threadIdx.x == 0) {
#pragma unroll
        for (int e = 0; e < NE; e++) g_offsets[e] = off[e];
        g_offsets[NE] = a;                  // NP (multiple of 128, <= NPAD)
    }
    int t = blockIdx.x * 256 + threadIdx.x;
    if (t < NTOK) {
        int e = g_expert[t];
        int pos = off[e] + atomicAdd(&g_cursor[e], 1);
        g_perm[pos] = t;
    }
}

// ---------------- fp16 HMMA GEMM core ----------------
// CTA tile 128x128, K-stage 64, 3-stage cp.async, 8 warps (4x2), warp tile 32x64,
// 2 CTAs/SM. All M-tiles full (padded layout) -> no row masks anywhere.
#define NST 3
#define A_BYT (128 * 128)            // 16KB
#define B_BYT (64 * 256)             // 16KB
#define ST_BYT (A_BYT + B_BYT)       // 32768
#define GEMM_SMEM (NST * ST_BYT + 512)

template <int EPI, bool PERM>
__device__ __forceinline__ void gemm_core(
    const __half* __restrict__ A, int lda,
    const __half* __restrict__ B, int ldb,
    const float* __restrict__ bias,
    int K,
    __half* __restrict__ outH, int ldc,
    int m0, int n0, char* smem, const int* __restrict__ perm)
{
    const int tid = threadIdx.x;
    const int lane = tid & 31, wid = tid >> 5;
    const int wm = wid >> 1, wn = wid & 1;      // 4 x 2 warp grid

    int* s_perm = (int*)(smem + NST * ST_BYT);
    if (PERM) {
        if (tid < 128) {
            int p = perm[m0 + tid];
            s_perm[tid] = (p < 0) ? 0 : p;      // pad rows -> any valid row (garbage, skipped later)
        }
        __syncthreads();
    }

    float acc[2][8][4];
#pragma unroll
    for (int i = 0; i < 2; i++)
#pragma unroll
        for (int j = 0; j < 8; j++)
#pragma unroll
            for (int k = 0; k < 4; k++) acc[i][j][k] = 0.f;

    const int nk = K >> 6;

    auto load_stage = [&](int s) {
        char* base = smem + (s % NST) * ST_BYT;
        __half* as = (__half*)base;
        __half* bs = (__half*)(base + A_BYT);
        const int k0 = s << 6;
#pragma unroll
        for (int i = 0; i < 4; i++) {            // A: 128 rows x 8 granules of 16B
            int c = tid + (i << 8);
            int r = c >> 3, g = c & 7;
            const __half* src = PERM
                ? A + (size_t)s_perm[r] * lda + k0 + (g << 3)
                : A + (size_t)(m0 + r) * lda + k0 + (g << 3);
            cpa16(as + r * 64 + ((g ^ (r & 7)) << 3), src);
        }
#pragma unroll
        for (int i = 0; i < 4; i++) {            // B: 64 rows x 16 granules of 16B
            int c = tid + (i << 8);
            int r = c >> 4, g = c & 15;
            cpa16(bs + r * 128 + ((g ^ (r & 7)) << 3),
                  B + (size_t)(k0 + r) * ldb + n0 + (g << 3));
        }
        asm volatile("cp.async.commit_group;" ::: "memory");
    };

    load_stage(0);
    load_stage(1);

    for (int kt = 0; kt < nk; kt++) {
        if (kt + 1 < nk) {
            asm volatile("cp.async.wait_group 1;" ::: "memory");
        } else {
            asm volatile("cp.async.wait_group 0;" ::: "memory");
        }
        __syncthreads();                         // stage kt ready AND buffer (kt+2)%3 free
        if (kt + 2 < nk) load_stage(kt + 2);

        char* base = smem + (kt % NST) * ST_BYT;
        __half* as = (__half*)base;
        __half* bs = (__half*)(base + A_BYT);
#pragma unroll
        for (int ks = 0; ks < 4; ks++) {
            const int kk = ks << 4;
            uint32_t af[2][4];
#pragma unroll
            for (int mi = 0; mi < 2; mi++) {
                int mr = wm * 32 + mi * 16 + (lane & 15);
                int g = (kk >> 3) + (lane >> 4);
                ldsm4(af[mi][0], af[mi][1], af[mi][2], af[mi][3],
                      as + mr * 64 + ((g ^ (mr & 7)) << 3));
            }
            uint32_t bf[8][2];
#pragma unroll
            for (int nj = 0; nj < 4; nj++) {
                int kr = kk + (lane & 15);
                int g = wn * 8 + nj * 2 + (lane >> 4);
                ldsm4t(bf[2 * nj][0], bf[2 * nj][1], bf[2 * nj + 1][0], bf[2 * nj + 1][1],
                       bs + kr * 128 + ((g ^ (kr & 7)) << 3));
            }
#pragma unroll
            for (int mi = 0; mi < 2; mi++)
#pragma unroll
                for (int ni = 0; ni < 8; ni++)
                    mma16816(acc[mi][ni], af[mi], bf[ni]);
        }
    }

    // epilogue (no row mask: all tile rows storeable by construction)
    const int gq = lane >> 2, tq = lane & 3;
#pragma unroll
    for (int mi = 0; mi < 2; mi++) {
#pragma unroll
        for (int rr = 0; rr < 2; rr++) {
            int grow = m0 + wm * 32 + mi * 16 + gq + rr * 8;
#pragma unroll
            for (int ni = 0; ni < 8; ni++) {
                int col = n0 + wn * 64 + ni * 8 + tq * 2;
                float v0 = acc[mi][ni][rr * 2 + 0] + bias[col];
                float v1 = acc[mi][ni][rr * 2 + 1] + bias[col + 1];
                if (EPI == 1) { v0 = gelu_exact(v0); v1 = gelu_exact(v1); }
                *(__half2*)(outH + (size_t)grow * ldc + col) = __floats2half2_rn(v0, v1);
            }
        }
    }
}

// ---------------- launch 4: grouped GEMM1 over padded flat grid ----------------
__global__ __launch_bounds__(256, 2) void gemm1_kernel(const float* __restrict__ b1) {
    extern __shared__ char smem[];
    int m0 = blockIdx.y << 7;
    if (m0 >= g_offsets[NE]) return;
    int e = 0;
    while (m0 >= g_offsets[e + 1]) e++;          // padded offsets, monotone; e <= 7
    gemm_core<1, true>(g_xh, HD,
                       g_W1h + (size_t)e * HD * ID, ID,
                       b1 + (size_t)e * ID, HD,
                       g_inter, ID,
                       m0, blockIdx.x << 7, smem, g_perm);
}

// ---------------- launch 5: dense GEMM2 over padded rows ----------------
__global__ __launch_bounds__(256, 2) void gemm2_kernel(const float* __restrict__ bo) {
    extern __shared__ char smem[];
    int m0 = blockIdx.y << 7;
    if (m0 >= g_offsets[NE]) return;
    gemm_core<2, false>(g_inter, ID, g_Woh, HD, bo, ID,
                        g_yh, HD, m0, blockIdx.x << 7, smem, nullptr);
}

// ---------------- launch 6: LayerNorm, exact fp32 residual, un-permute, skip pads ----------------
__global__ void ln_kernel(const float* __restrict__ x, const float* __restrict__ gamma,
                          const float* __restrict__ beta, float* __restrict__ out) {
    int pos = blockIdx.x;
    int tok = g_perm[pos];
    if (tok < 0) return;                         // pad slot (or beyond NP)
    const __half2* yr = (const __half2*)(g_yh + (size_t)pos * HD);
    const float2* xr = (const float2*)(x + (size_t)tok * HD);
    int tid = threadIdx.x;
    float2 v[2]; float s = 0.f, s2 = 0.f;
#pragma unroll
    for (int j = 0; j < 2; j++) {
        int i = tid + j * 256;                   // half2 index, 512 pairs per row
        float2 yv = __half22float2(yr[i]);
        float2 xv = xr[i];
        v[j].x = yv.x + xv.x; v[j].y = yv.y + xv.y;
        s += v[j].x + v[j].y;
        s2 += v[j].x * v[j].x + v[j].y * v[j].y;
    }
    __shared__ float red[64];
#pragma unroll
    for (int o = 16; o > 0; o >>= 1) {
        s  += __shfl_xor_sync(0xffffffffu, s, o);
        s2 += __shfl_xor_sync(0xffffffffu, s2, o);
    }
    int w = tid >> 5;
    if ((tid & 31) == 0) { red[w] = s; red[32 + w] = s2; }
    __syncthreads();
    if (tid < 32) {
        float a = (tid < 8) ? red[tid] : 0.f;
        float b = (tid < 8) ? red[32 + tid] : 0.f;
#pragma unroll
        for (int o = 4; o > 0; o >>= 1) {
            a += __shfl_xor_sync(0xffffffffu, a, o);
            b += __shfl_xor_sync(0xffffffffu, b, o);
        }
        if (tid == 0) { red[0] = a; red[32] = b; }
    }
    __syncthreads();
    float mu = red[0] * (1.0f / HD);
    float var = red[32] * (1.0f / HD) - mu * mu;
    float rs = rsqrtf(var + 1e-12f);
    float2* orow = (float2*)(out + (size_t)tok * HD);
    const float2* g2 = (const float2*)gamma;
    const float2* b2 = (const float2*)beta;
#pragma unroll
    for (int j = 0; j < 2; j++) {
        int i = tid + j * 256;
        float2 gv = g2[i], bv = b2[i], o2;
        o2.x = (v[j].x - mu) * rs * gv.x + bv.x;
        o2.y = (v[j].y - mu) * rs * gv.y + bv.y;
        orow[i] = o2;
    }
}

// ---------------- launch ----------------
extern "C" void kernel_launch(void* const* d_in, const int* in_sizes, int n_in,
                              void* d_out, int out_size) {
    const float* x     = (const float*)d_in[0];
    const float* Wr    = (const float*)d_in[1];
    const float* W1    = (const float*)d_in[2];
    const float* b1    = (const float*)d_in[3];
    const float* Wo    = (const float*)d_in[4];
    const float* bo    = (const float*)d_in[5];
    const float* gamma = (const float*)d_in[6];
    const float* beta  = (const float*)d_in[7];
    float* out = (float*)d_out;
    (void)in_sizes; (void)n_in; (void)out_size;

    cudaFuncSetAttribute(gemm1_kernel, cudaFuncAttributeMaxDynamicSharedMemorySize, GEMM_SMEM);
    cudaFuncSetAttribute(gemm2_kernel, cudaFuncAttributeMaxDynamicSharedMemorySize, GEMM_SMEM);

    convert_kernel<<<45056, 256>>>((const float4*)W1, (const float4*)Wo, (const float4*)x);  // 1
    router_kernel<<<1024, 256>>>(x, Wr);                                                     // 2
    scatter_kernel<<<32, 256>>>();                                                           // 3

    dim3 g1(ID / 128, NPAD / 128, 1);    // 32 x 72, flat padded grid; all live tiles full
    gemm1_kernel<<<g1, 256, GEMM_SMEM>>>(b1);                                                // 4 (ncu target)

    dim3 g2(HD / 128, NPAD / 128, 1);    // 8 x 72
    gemm2_kernel<<<g2, 256, GEMM_SMEM>>>(bo);                                                // 5

    ln_kernel<<<NPAD, 256>>>(x, gamma, beta, out);                                           // 6
}